// round 10
// baseline (speedup 1.0000x reference)
#include <cuda_runtime.h>
#include <math.h>

#define SD     16
#define IDIM   64
#define ODIM   64
#define NBATCH 32
#define SEQLEN 8192
#define LCH    32
#define NCH    (SEQLEN/LCH)          /* 256 chunks per batch */
#define DTVAL  1.0f
#define FULLMASK 0xffffffffu

__device__ __align__(16) float g_Ad[SD*SD];
__device__ __align__(16) float g_AdL[SD*SD];              // A_d^LCH
__device__ __align__(16) float g_Bd[SD*IDIM];
__device__ __align__(16) float g_Apow[LCH*SD*SD];         // A_d^{j+1}, j=0..LCH-1
__device__ __align__(16) float g_H[NBATCH*SEQLEN*SD];
__device__ __align__(16) float g_hprev[NBATCH*NCH*SD];

__global__ void knop() {}

// ---------------- K0: discretization + A powers by doubling (1 block, 256 thr) ----------------
__global__ void k0_setup(const float* __restrict__ ll, const float* __restrict__ p,
                         const float* __restrict__ q,  const float* __restrict__ B,
                         const float* __restrict__ P) {
    __shared__ float core[SD*SD], tmp[SD*SD], Ac[SD*SD];
    __shared__ float aug[SD][96];
    __shared__ float fvec[SD];
    __shared__ float prow[96];
    int t = threadIdx.x;

    if (t < SD*SD) {
        int i = t >> 4, j = t & 15;
        float v = p[i] * q[j];
        if (i == j) v -= expf(ll[i]);
        core[t] = v;
    }
    __syncthreads();
    if (t < SD*SD) {
        int i = t >> 4, j = t & 15;
        float s = 0.f;
        for (int k = 0; k < SD; k++) s += P[i*SD+k] * core[k*SD+j];
        tmp[t] = s;
    }
    __syncthreads();
    if (t < SD*SD) {
        int i = t >> 4, j = t & 15;
        float s = 0.f;
        for (int k = 0; k < SD; k++) s += tmp[i*SD+k] * P[j*SD+k];
        Ac[t] = s;
    }
    __syncthreads();
    for (int f = t; f < SD*96; f += 256) {
        int r = f / 96, c = f % 96;
        float v;
        if (c < 16)      v = (r == c      ? 1.f : 0.f) - 0.5f*DTVAL*Ac[r*SD+c];
        else if (c < 32) v = (r == (c-16) ? 1.f : 0.f) + 0.5f*DTVAL*Ac[r*SD+(c-16)];
        else             v = DTVAL * B[r*IDIM + (c-32)];
        aug[r][c] = v;
    }
    __syncthreads();
    for (int col = 0; col < SD; col++) {
        if (t < 96) prow[t] = aug[col][t];
        if (t < SD) fvec[t] = aug[t][col];
        __syncthreads();
        float ipv = 1.f / prow[col];
        for (int f = t; f < SD*96; f += 256) {
            int r = f / 96, c = f % 96;
            if (r == col) aug[r][c] = prow[c] * ipv;
            else          aug[r][c] = fmaf(-fvec[r]*ipv, prow[c], aug[r][c]);
        }
        __syncthreads();
    }
    if (t < SD*SD) { int r = t >> 4, c = t & 15; float v = aug[r][16+c]; g_Ad[t] = v; g_Apow[t] = v; }
    for (int f = t; f < SD*IDIM; f += 256) { int r = f / IDIM, c = f % IDIM; g_Bd[f] = aug[r][32+c]; }
    __syncthreads();
    for (int m = 1; m <= LCH/2; m <<= 1) {
        for (int f = t; f < m*256; f += 256) {
            int i = f >> 8, e = f & 255, r = e >> 4, c2 = e & 15;
            const float* L = g_Apow + i*256 + r*16;
            const float* R = g_Apow + (m-1)*256;
            float s = 0.f;
#pragma unroll
            for (int k = 0; k < 16; k++) s = fmaf(L[k], R[k*16 + c2], s);
            g_Apow[(m+i)*256 + e] = s;
        }
        __syncthreads();
    }
    if (t < SD*SD) g_AdL[t] = g_Apow[(LCH-1)*256 + t];
}

// ---------------- kBxS: u = x @ Bd^T then in-smem local scan, fused ----------------
// Block = 128 rows = 4 chunks of 32. GEMM -> Us (smem) -> scan in smem -> one coalesced store.
#define XSTR 68
#define USTR 20
__global__ void __launch_bounds__(256) kbxs(const float* __restrict__ x) {
    __shared__ __align__(16) float Xs[128*XSTR];   // 34.8 KB, reused as Us
    __shared__ float Bs[16*66];
    __shared__ float As[16*17];
    int tid = threadIdx.x;
    size_t row0 = (size_t)blockIdx.x * 128;

    for (int i = tid; i < SD*IDIM; i += 256) {
        int nn = i >> 6, kk = i & 63;
        Bs[nn*66 + kk] = g_Bd[i];
    }
    if (tid < SD*SD) As[(tid >> 4)*17 + (tid & 15)] = g_Ad[tid];
#pragma unroll
    for (int i = 0; i < 8; i++) {
        int f = tid + 256*i;
        int r = f >> 4, qq = f & 15;
        float4 v = *(const float4*)(x + (row0 + r)*64 + qq*4);
        *(float4*)&Xs[r*XSTR + qq*4] = v;
    }
    __syncthreads();

    // ---- GEMM: u[row][n] = sum_k x[row][k] Bd[n][k] ----
    int tr = tid >> 3, tc = tid & 7;
    unsigned long long acc[4][2];
#pragma unroll
    for (int m = 0; m < 4; m++) { acc[m][0] = 0ull; acc[m][1] = 0ull; }
    const float* xa = Xs + (tr*4)*XSTR;
#pragma unroll
    for (int kp = 0; kp < 32; kp++) {
        unsigned long long a2[4], b2[2];
#pragma unroll
        for (int m = 0; m < 4; m++)
            a2[m] = *(const unsigned long long*)(xa + m*XSTR + 2*kp);
        b2[0] = *(const unsigned long long*)(Bs + tc*66 + 2*kp);
        b2[1] = *(const unsigned long long*)(Bs + (tc+8)*66 + 2*kp);
#pragma unroll
        for (int m = 0; m < 4; m++) {
            asm("fma.rn.f32x2 %0, %1, %2, %0;" : "+l"(acc[m][0]) : "l"(a2[m]), "l"(b2[0]));
            asm("fma.rn.f32x2 %0, %1, %2, %0;" : "+l"(acc[m][1]) : "l"(a2[m]), "l"(b2[1]));
        }
    }
    __syncthreads();                                // all Xs reads done
    float* Us = Xs;                                 // reuse as 128 x USTR
#pragma unroll
    for (int m = 0; m < 4; m++) {
#pragma unroll
        for (int c = 0; c < 2; c++) {
            float lo, hi;
            asm("mov.b64 {%0,%1}, %2;" : "=f"(lo), "=f"(hi) : "l"(acc[m][c]));
            Us[(tr*4 + m)*USTR + tc + 8*c] = lo + hi;
        }
    }
    __syncthreads();

    // ---- local scan in smem: warps 0-1, half-warp per chunk ----
    if (tid < 64) {
        int hw = tid >> 4, n = tid & 15;
        float Ar[16];
#pragma unroll
        for (int k = 0; k < 16; k++) Ar[k] = As[n*17 + k];
        float* u = Us + hw*32*USTR + n;
        float h = 0.f;
        float uc = u[0];
#pragma unroll
        for (int i = 0; i < LCH; i++) {
            float un = (i < LCH-1) ? u[(i+1)*USTR] : 0.f;
            float acc0 = uc, acc1 = 0.f, acc2 = 0.f, acc3 = 0.f;
#pragma unroll
            for (int m = 0; m < 16; m += 4) {
                acc0 = fmaf(Ar[m],   __shfl_sync(FULLMASK, h, m,   16), acc0);
                acc1 = fmaf(Ar[m+1], __shfl_sync(FULLMASK, h, m+1, 16), acc1);
                acc2 = fmaf(Ar[m+2], __shfl_sync(FULLMASK, h, m+2, 16), acc2);
                acc3 = fmaf(Ar[m+3], __shfl_sync(FULLMASK, h, m+3, 16), acc3);
            }
            h = (acc0 + acc1) + (acc2 + acc3);
            u[i*USTR] = h;
            uc = un;
        }
    }
    __syncthreads();

    // ---- coalesced store of 128x16 local h ----
#pragma unroll
    for (int i = 0; i < 2; i++) {
        int f = tid + 256*i;
        int r = f >> 2, qq = f & 3;
        float4 v = *(const float4*)&Us[r*USTR + qq*4];
        *(float4*)(g_H + row0*SD + (size_t)f*4) = v;
    }
}

// ---------------- K2: boundary scan across chunks (warp per batch) ----------------
__global__ void k2_scan() {
    __shared__ float ss[NCH*SD];                     // 16 KB
    int b = blockIdx.x;
    int lane = threadIdx.x;
    int n = lane & 15;
    for (int f = lane; f < NCH*SD; f += 32) {
        int c = f >> 4, nn = f & 15;
        ss[f] = g_H[((size_t)b*SEQLEN + (size_t)c*LCH + (LCH-1))*SD + nn];
    }
    __syncwarp();
    float AL[16];
    {
        const float4* ap = (const float4*)(g_AdL + n*SD);
#pragma unroll
        for (int i = 0; i < 4; i++) { float4 v = ap[i]; AL[4*i]=v.x; AL[4*i+1]=v.y; AL[4*i+2]=v.z; AL[4*i+3]=v.w; }
    }
    float h = 0.f;
    for (int c = 0; c < NCH; c++) {
        if (lane < 16) g_hprev[((size_t)b*NCH + c)*SD + n] = h;
        float h0 = ss[c*SD + n], h1 = 0.f;
#pragma unroll
        for (int m = 0; m < 16; m += 2) {
            h0 = fmaf(AL[m],   __shfl_sync(FULLMASK, h, m),   h0);
            h1 = fmaf(AL[m+1], __shfl_sync(FULLMASK, h, m+1), h1);
        }
        h = h0 + h1;
    }
}

// ---------------- K2.5c: h_j += A^{j+1} h_prev, fully coalesced ----------------
#define K25_CHUNKS 8
#define PROW 17
__global__ void __launch_bounds__(256) k25c() {
    __shared__ float sA[16*16*PROW];
    __shared__ float shp[K25_CHUNKS*16];
    int t = threadIdx.x;
    int bx = blockIdx.x, by = blockIdx.y;
    int jloc = t >> 4, n = t & 15;

#pragma unroll
    for (int i = 0; i < 16; i++) {
        int f = t + 256*i;
        int jl = f >> 8, e = f & 255, r = e >> 4, c = e & 15;
        sA[jl*(16*PROW) + r*PROW + c] = g_Apow[(by*16 + jl)*256 + e];
    }
    if (t < K25_CHUNKS*16) shp[t] = g_hprev[bx*K25_CHUNKS*16 + t];
    __syncthreads();

    float a[16];
    {
        const float* Ar = sA + jloc*(16*PROW) + n*PROW;
#pragma unroll
        for (int k = 0; k < 16; k++) a[k] = Ar[k];
    }
#pragma unroll
    for (int ch = 0; ch < K25_CHUNKS; ch++) {
        const float* hp = shp + ch*16;
        float s = 0.f;
#pragma unroll
        for (int k = 0; k < 16; k++) s = fmaf(a[k], hp[k], s);
        g_H[(size_t)(bx*K25_CHUNKS + ch)*(LCH*SD) + by*256 + t] += s;
    }
}

// ---------------- K3: Y = [X|H] @ [D|C]^T with packed f32x2 FMA ----------------
#define WSTR 82
__global__ void __launch_bounds__(256, 2) k3_out(const float* __restrict__ x,
                                                 const float* __restrict__ C,
                                                 const float* __restrict__ D,
                                                 float* __restrict__ y) {
    __shared__ __align__(16) float Zs[128*40];
    __shared__ __align__(16) float Ws[64*WSTR];
    int tid = threadIdx.x;
    size_t row0 = (size_t)blockIdx.x * 128;
    int tr = tid >> 4, tc = tid & 15;

#pragma unroll
    for (int i = 0; i < 8; i++) {
        int f = tid + 256*i;
        int o = f >> 5, k0 = (f & 31) << 1;
        float2 v = *(const float2*)(D + o*64 + k0);
        *(float2*)&Ws[o*WSTR + k0] = v;
    }
#pragma unroll
    for (int i = 0; i < 2; i++) {
        int f = tid + 256*i;
        int o = f >> 3, k0 = (f & 7) << 1;
        float2 v = *(const float2*)(C + o*16 + k0);
        *(float2*)&Ws[o*WSTR + 64 + k0] = v;
    }

    unsigned long long acc[8][4];
#pragma unroll
    for (int m = 0; m < 8; m++)
#pragma unroll
        for (int c = 0; c < 4; c++) acc[m][c] = 0ull;

    const float* za = Zs + (tr*8)*40;

#pragma unroll 1
    for (int h = 0; h < 2; h++) {
        if (h == 0) {
#pragma unroll
            for (int i = 0; i < 5; i++) {
                int f = tid + 256*i;
                int r = f / 10, qq = f % 10;
                float4 v = *(const float4*)(x + (row0 + r)*64 + qq*4);
                *(float4*)&Zs[r*40 + qq*4] = v;
            }
        } else {
#pragma unroll
            for (int i = 0; i < 3; i++) {
                int f = tid + 256*i;
                if (f < 768) {
                    int r = f / 6, qq = f % 6;
                    float4 v = *(const float4*)(x + (row0 + r)*64 + 40 + qq*4);
                    *(float4*)&Zs[r*40 + qq*4] = v;
                }
            }
#pragma unroll
            for (int i = 0; i < 2; i++) {
                int f = tid + 256*i;
                int r = f >> 2, qq = f & 3;
                float4 v = *(const float4*)(g_H + (row0 + r)*16 + qq*4);
                *(float4*)&Zs[r*40 + 24 + qq*4] = v;
            }
        }
        __syncthreads();
        int kb = h * 40;
#pragma unroll
        for (int kp = 0; kp < 20; kp++) {
            unsigned long long a2[8], b2[4];
#pragma unroll
            for (int m = 0; m < 8; m++)
                a2[m] = *(const unsigned long long*)(za + m*40 + 2*kp);
#pragma unroll
            for (int c = 0; c < 4; c++)
                b2[c] = *(const unsigned long long*)(Ws + (tc + 16*c)*WSTR + kb + 2*kp);
#pragma unroll
            for (int m = 0; m < 8; m++)
#pragma unroll
                for (int c = 0; c < 4; c++)
                    asm("fma.rn.f32x2 %0, %1, %2, %0;"
                        : "+l"(acc[m][c]) : "l"(a2[m]), "l"(b2[c]));
        }
        __syncthreads();
    }

#pragma unroll
    for (int m = 0; m < 8; m++) {
        size_t row = row0 + tr*8 + m;
#pragma unroll
        for (int c = 0; c < 4; c++) {
            float lo, hi;
            asm("mov.b64 {%0,%1}, %2;" : "=f"(lo), "=f"(hi) : "l"(acc[m][c]));
            y[row*64 + tc + 16*c] = lo + hi;
        }
    }
}

extern "C" void kernel_launch(void* const* d_in, const int* in_sizes, int n_in,
                              void* d_out, int out_size) {
    const float* x  = (const float*)d_in[0];
    const float* ll = (const float*)d_in[1];
    const float* p  = (const float*)d_in[2];
    const float* q  = (const float*)d_in[3];
    const float* B  = (const float*)d_in[4];
    const float* C  = (const float*)d_in[5];
    const float* D  = (const float*)d_in[6];
    const float* P  = (const float*)d_in[7];
    float* y = (float*)d_out;

    k0_setup<<<1, 256>>>(ll, p, q, B, P);
    kbxs<<<(NBATCH*SEQLEN)/128, 256>>>(x);      // GEMM + local scan fused
    knop<<<1, 32>>>();
    k2_scan<<<NBATCH, 32>>>();                  // profiled slot (4th)
    dim3 g25(NBATCH*NCH/K25_CHUNKS, LCH/16);
    k25c<<<g25, 256>>>();
    k3_out<<<(NBATCH*SEQLEN)/128, 256>>>(x, C, D, y);
}

// round 11
// speedup vs baseline: 1.0471x; 1.0471x over previous
#include <cuda_runtime.h>
#include <math.h>

#define SD     16
#define IDIM   64
#define ODIM   64
#define NBATCH 32
#define SEQLEN 8192
#define LCH    32
#define NCH    (SEQLEN/LCH)          /* 256 chunks per batch */
#define NSUP   16                    /* chunks per superchunk */
#define NSC    (NCH/NSUP)            /* 16 superchunks per batch */
#define DTVAL  1.0f
#define FULLMASK 0xffffffffu

__device__ __align__(16) float g_Ad[SD*SD];
__device__ __align__(16) float g_Bd[SD*IDIM];
__device__ __align__(16) float g_Apow[LCH*SD*SD];          // A^{j+1}, j=0..31
__device__ __align__(16) float g_ALpow[17*SD*SD];          // (A^32)^j, j=0..16
__device__ __align__(16) float g_H[NBATCH*SEQLEN*SD];
__device__ __align__(16) float g_hprev[NBATCH*NCH*SD];
__device__ __align__(16) float g_Pfx[NBATCH*NSC*17*SD];    // local prefixes P_0..P_16
__device__ __align__(16) float g_Hsup[NBATCH*NSC*SD];      // superchunk boundary states

__global__ void knop() {}

// ---------------- K0: discretization + power tables (1 block, 256 thr) ----------------
__global__ void k0_setup(const float* __restrict__ ll, const float* __restrict__ p,
                         const float* __restrict__ q,  const float* __restrict__ B,
                         const float* __restrict__ P) {
    __shared__ float core[SD*SD], tmp[SD*SD], Ac[SD*SD];
    __shared__ float aug[SD][96];
    __shared__ float fvec[SD];
    __shared__ float prow[96];
    int t = threadIdx.x;

    if (t < SD*SD) {
        int i = t >> 4, j = t & 15;
        float v = p[i] * q[j];
        if (i == j) v -= expf(ll[i]);
        core[t] = v;
    }
    __syncthreads();
    if (t < SD*SD) {
        int i = t >> 4, j = t & 15;
        float s = 0.f;
        for (int k = 0; k < SD; k++) s += P[i*SD+k] * core[k*SD+j];
        tmp[t] = s;
    }
    __syncthreads();
    if (t < SD*SD) {
        int i = t >> 4, j = t & 15;
        float s = 0.f;
        for (int k = 0; k < SD; k++) s += tmp[i*SD+k] * P[j*SD+k];
        Ac[t] = s;
    }
    __syncthreads();
    for (int f = t; f < SD*96; f += 256) {
        int r = f / 96, c = f % 96;
        float v;
        if (c < 16)      v = (r == c      ? 1.f : 0.f) - 0.5f*DTVAL*Ac[r*SD+c];
        else if (c < 32) v = (r == (c-16) ? 1.f : 0.f) + 0.5f*DTVAL*Ac[r*SD+(c-16)];
        else             v = DTVAL * B[r*IDIM + (c-32)];
        aug[r][c] = v;
    }
    __syncthreads();
    for (int col = 0; col < SD; col++) {
        if (t < 96) prow[t] = aug[col][t];
        if (t < SD) fvec[t] = aug[t][col];
        __syncthreads();
        float ipv = 1.f / prow[col];
        for (int f = t; f < SD*96; f += 256) {
            int r = f / 96, c = f % 96;
            if (r == col) aug[r][c] = prow[c] * ipv;
            else          aug[r][c] = fmaf(-fvec[r]*ipv, prow[c], aug[r][c]);
        }
        __syncthreads();
    }
    if (t < SD*SD) { int r = t >> 4, c = t & 15; float v = aug[r][16+c]; g_Ad[t] = v; g_Apow[t] = v; }
    for (int f = t; f < SD*IDIM; f += 256) { int r = f / IDIM, c = f % IDIM; g_Bd[f] = aug[r][32+c]; }
    __syncthreads();
    // A^1..A^32 by doubling
    for (int m = 1; m <= LCH/2; m <<= 1) {
        for (int f = t; f < m*256; f += 256) {
            int i = f >> 8, e = f & 255, r = e >> 4, c2 = e & 15;
            const float* L = g_Apow + i*256 + r*16;
            const float* R = g_Apow + (m-1)*256;
            float s = 0.f;
#pragma unroll
            for (int k = 0; k < 16; k++) s = fmaf(L[k], R[k*16 + c2], s);
            g_Apow[(m+i)*256 + e] = s;
        }
        __syncthreads();
    }
    // AL^0..AL^16 (AL = A^32) by doubling
    if (t < 256) {
        int r = t >> 4, c = t & 15;
        g_ALpow[t] = (r == c) ? 1.f : 0.f;
        g_ALpow[256 + t] = g_Apow[(LCH-1)*256 + t];
    }
    __syncthreads();
    for (int m = 1; m <= 8; m <<= 1) {
        for (int f = t; f < m*256; f += 256) {
            int i = (f >> 8) + 1, e = f & 255, r = e >> 4, c2 = e & 15;
            const float* L = g_ALpow + i*256 + r*16;
            const float* R = g_ALpow + m*256;
            float s = 0.f;
#pragma unroll
            for (int k = 0; k < 16; k++) s = fmaf(L[k], R[k*16 + c2], s);
            g_ALpow[(m+i)*256 + e] = s;
        }
        __syncthreads();
    }
}

// ---------------- kBxS: u = x @ Bd^T + in-smem local scan (fused) ----------------
#define XSTR 68
#define USTR 20
__global__ void __launch_bounds__(256) kbxs(const float* __restrict__ x) {
    __shared__ __align__(16) float Xs[128*XSTR];
    __shared__ float Bs[16*66];
    __shared__ float As[16*17];
    int tid = threadIdx.x;
    size_t row0 = (size_t)blockIdx.x * 128;

    for (int i = tid; i < SD*IDIM; i += 256) {
        int nn = i >> 6, kk = i & 63;
        Bs[nn*66 + kk] = g_Bd[i];
    }
    if (tid < SD*SD) As[(tid >> 4)*17 + (tid & 15)] = g_Ad[tid];
#pragma unroll
    for (int i = 0; i < 8; i++) {
        int f = tid + 256*i;
        int r = f >> 4, qq = f & 15;
        float4 v = *(const float4*)(x + (row0 + r)*64 + qq*4);
        *(float4*)&Xs[r*XSTR + qq*4] = v;
    }
    __syncthreads();

    int tr = tid >> 3, tc = tid & 7;
    unsigned long long acc[4][2];
#pragma unroll
    for (int m = 0; m < 4; m++) { acc[m][0] = 0ull; acc[m][1] = 0ull; }
    const float* xa = Xs + (tr*4)*XSTR;
#pragma unroll
    for (int kp = 0; kp < 32; kp++) {
        unsigned long long a2[4], b2[2];
#pragma unroll
        for (int m = 0; m < 4; m++)
            a2[m] = *(const unsigned long long*)(xa + m*XSTR + 2*kp);
        b2[0] = *(const unsigned long long*)(Bs + tc*66 + 2*kp);
        b2[1] = *(const unsigned long long*)(Bs + (tc+8)*66 + 2*kp);
#pragma unroll
        for (int m = 0; m < 4; m++) {
            asm("fma.rn.f32x2 %0, %1, %2, %0;" : "+l"(acc[m][0]) : "l"(a2[m]), "l"(b2[0]));
            asm("fma.rn.f32x2 %0, %1, %2, %0;" : "+l"(acc[m][1]) : "l"(a2[m]), "l"(b2[1]));
        }
    }
    __syncthreads();
    float* Us = Xs;
#pragma unroll
    for (int m = 0; m < 4; m++) {
#pragma unroll
        for (int c = 0; c < 2; c++) {
            float lo, hi;
            asm("mov.b64 {%0,%1}, %2;" : "=f"(lo), "=f"(hi) : "l"(acc[m][c]));
            Us[(tr*4 + m)*USTR + tc + 8*c] = lo + hi;
        }
    }
    __syncthreads();

    if (tid < 64) {
        int hw = tid >> 4, n = tid & 15;
        float Ar[16];
#pragma unroll
        for (int k = 0; k < 16; k++) Ar[k] = As[n*17 + k];
        float* u = Us + hw*32*USTR + n;
        float h = 0.f;
        float uc = u[0];
#pragma unroll
        for (int i = 0; i < LCH; i++) {
            float un = (i < LCH-1) ? u[(i+1)*USTR] : 0.f;
            float acc0 = uc, acc1 = 0.f, acc2 = 0.f, acc3 = 0.f;
#pragma unroll
            for (int m = 0; m < 16; m += 4) {
                acc0 = fmaf(Ar[m],   __shfl_sync(FULLMASK, h, m,   16), acc0);
                acc1 = fmaf(Ar[m+1], __shfl_sync(FULLMASK, h, m+1, 16), acc1);
                acc2 = fmaf(Ar[m+2], __shfl_sync(FULLMASK, h, m+2, 16), acc2);
                acc3 = fmaf(Ar[m+3], __shfl_sync(FULLMASK, h, m+3, 16), acc3);
            }
            h = (acc0 + acc1) + (acc2 + acc3);
            u[i*USTR] = h;
            uc = un;
        }
    }
    __syncthreads();

#pragma unroll
    for (int i = 0; i < 2; i++) {
        int f = tid + 256*i;
        int r = f >> 2, qq = f & 3;
        float4 v = *(const float4*)&Us[r*USTR + qq*4];
        *(float4*)(g_H + row0*SD + (size_t)f*4) = v;
    }
}

// ---------------- k2a: local prefixes within superchunks (512 half-warps) ----------------
__global__ void __launch_bounds__(256) k2a() {
    int tid = threadIdx.x;
    int g = blockIdx.x * 16 + (tid >> 4);      // superchunk id 0..511
    int n = tid & 15;
    float Ar[16];
#pragma unroll
    for (int k = 0; k < 16; k++) Ar[k] = g_ALpow[256 + n*16 + k];   // AL row n

    float Pv = 0.f;
#pragma unroll
    for (int j = 0; j < NSUP; j++) {
        g_Pfx[(g*17 + j)*16 + n] = Pv;
        int c = g*NSUP + j;
        float s = g_H[((size_t)c*LCH + (LCH-1))*SD + n];   // chunk summary
        float acc0 = s, acc1 = 0.f, acc2 = 0.f, acc3 = 0.f;
#pragma unroll
        for (int m = 0; m < 16; m += 4) {
            acc0 = fmaf(Ar[m],   __shfl_sync(FULLMASK, Pv, m,   16), acc0);
            acc1 = fmaf(Ar[m+1], __shfl_sync(FULLMASK, Pv, m+1, 16), acc1);
            acc2 = fmaf(Ar[m+2], __shfl_sync(FULLMASK, Pv, m+2, 16), acc2);
            acc3 = fmaf(Ar[m+3], __shfl_sync(FULLMASK, Pv, m+3, 16), acc3);
        }
        Pv = (acc0 + acc1) + (acc2 + acc3);
    }
    g_Pfx[(g*17 + 16)*16 + n] = Pv;
}

// ---------------- k2b: scan across superchunks (one half-warp per batch) ----------------
__global__ void __launch_bounds__(256) k2b() {
    int tid = threadIdx.x;
    int b = blockIdx.x * 16 + (tid >> 4);      // batch 0..31
    int n = tid & 15;
    float Ar[16];
#pragma unroll
    for (int k = 0; k < 16; k++) Ar[k] = g_ALpow[16*256 + n*16 + k];  // AL^16 row n

    float H = 0.f;
#pragma unroll
    for (int s = 0; s < NSC; s++) {
        int g = b*NSC + s;
        g_Hsup[g*16 + n] = H;
        float P16 = g_Pfx[(g*17 + 16)*16 + n];
        float acc0 = P16, acc1 = 0.f, acc2 = 0.f, acc3 = 0.f;
#pragma unroll
        for (int m = 0; m < 16; m += 4) {
            acc0 = fmaf(Ar[m],   __shfl_sync(FULLMASK, H, m,   16), acc0);
            acc1 = fmaf(Ar[m+1], __shfl_sync(FULLMASK, H, m+1, 16), acc1);
            acc2 = fmaf(Ar[m+2], __shfl_sync(FULLMASK, H, m+2, 16), acc2);
            acc3 = fmaf(Ar[m+3], __shfl_sync(FULLMASK, H, m+3, 16), acc3);
        }
        H = (acc0 + acc1) + (acc2 + acc3);
    }
}

// ---------------- k2c: hprev_c = AL^j Hsup + P_j (512 blocks, parallel) ----------------
#define PROW 17
__global__ void __launch_bounds__(256) k2c() {
    __shared__ float sA[16*16*PROW];           // AL^0..AL^15, padded
    __shared__ float sH[16];
    int t = threadIdx.x;
    int g = blockIdx.x;
    int j = t >> 4, n = t & 15;

#pragma unroll
    for (int i = 0; i < 16; i++) {
        int f = t + 256*i;
        int jl = f >> 8, e = f & 255, r = e >> 4, c = e & 15;
        sA[jl*(16*PROW) + r*PROW + c] = g_ALpow[jl*256 + e];
    }
    if (t < 16) sH[t] = g_Hsup[g*16 + t];
    __syncthreads();

    const float* Ar = sA + j*(16*PROW) + n*PROW;
    float s = g_Pfx[g*272 + t];                // P_j[n], coalesced
#pragma unroll
    for (int k = 0; k < 16; k++) s = fmaf(Ar[k], sH[k], s);
    g_hprev[g*256 + t] = s;
}

// ---------------- K2.5c: h_j += A^{j+1} h_prev, fully coalesced ----------------
#define K25_CHUNKS 8
__global__ void __launch_bounds__(256) k25c() {
    __shared__ float sA[16*16*PROW];
    __shared__ float shp[K25_CHUNKS*16];
    int t = threadIdx.x;
    int bx = blockIdx.x, by = blockIdx.y;
    int jloc = t >> 4, n = t & 15;

#pragma unroll
    for (int i = 0; i < 16; i++) {
        int f = t + 256*i;
        int jl = f >> 8, e = f & 255, r = e >> 4, c = e & 15;
        sA[jl*(16*PROW) + r*PROW + c] = g_Apow[(by*16 + jl)*256 + e];
    }
    if (t < K25_CHUNKS*16) shp[t] = g_hprev[bx*K25_CHUNKS*16 + t];
    __syncthreads();

    float a[16];
    {
        const float* Ar = sA + jloc*(16*PROW) + n*PROW;
#pragma unroll
        for (int k = 0; k < 16; k++) a[k] = Ar[k];
    }
#pragma unroll
    for (int ch = 0; ch < K25_CHUNKS; ch++) {
        const float* hp = shp + ch*16;
        float s = 0.f;
#pragma unroll
        for (int k = 0; k < 16; k++) s = fmaf(a[k], hp[k], s);
        g_H[(size_t)(bx*K25_CHUNKS + ch)*(LCH*SD) + by*256 + t] += s;
    }
}

// ---------------- K3: Y = [X|H] @ [D|C]^T with packed f32x2 FMA ----------------
#define WSTR 82
__global__ void __launch_bounds__(256, 2) k3_out(const float* __restrict__ x,
                                                 const float* __restrict__ C,
                                                 const float* __restrict__ D,
                                                 float* __restrict__ y) {
    __shared__ __align__(16) float Zs[128*40];
    __shared__ __align__(16) float Ws[64*WSTR];
    int tid = threadIdx.x;
    size_t row0 = (size_t)blockIdx.x * 128;
    int tr = tid >> 4, tc = tid & 15;

#pragma unroll
    for (int i = 0; i < 8; i++) {
        int f = tid + 256*i;
        int o = f >> 5, k0 = (f & 31) << 1;
        float2 v = *(const float2*)(D + o*64 + k0);
        *(float2*)&Ws[o*WSTR + k0] = v;
    }
#pragma unroll
    for (int i = 0; i < 2; i++) {
        int f = tid + 256*i;
        int o = f >> 3, k0 = (f & 7) << 1;
        float2 v = *(const float2*)(C + o*16 + k0);
        *(float2*)&Ws[o*WSTR + 64 + k0] = v;
    }

    unsigned long long acc[8][4];
#pragma unroll
    for (int m = 0; m < 8; m++)
#pragma unroll
        for (int c = 0; c < 4; c++) acc[m][c] = 0ull;

    const float* za = Zs + (tr*8)*40;

#pragma unroll 1
    for (int h = 0; h < 2; h++) {
        if (h == 0) {
#pragma unroll
            for (int i = 0; i < 5; i++) {
                int f = tid + 256*i;
                int r = f / 10, qq = f % 10;
                float4 v = *(const float4*)(x + (row0 + r)*64 + qq*4);
                *(float4*)&Zs[r*40 + qq*4] = v;
            }
        } else {
#pragma unroll
            for (int i = 0; i < 3; i++) {
                int f = tid + 256*i;
                if (f < 768) {
                    int r = f / 6, qq = f % 6;
                    float4 v = *(const float4*)(x + (row0 + r)*64 + 40 + qq*4);
                    *(float4*)&Zs[r*40 + qq*4] = v;
                }
            }
#pragma unroll
            for (int i = 0; i < 2; i++) {
                int f = tid + 256*i;
                int r = f >> 2, qq = f & 3;
                float4 v = *(const float4*)(g_H + (row0 + r)*16 + qq*4);
                *(float4*)&Zs[r*40 + 24 + qq*4] = v;
            }
        }
        __syncthreads();
        int kb = h * 40;
#pragma unroll
        for (int kp = 0; kp < 20; kp++) {
            unsigned long long a2[8], b2[4];
#pragma unroll
            for (int m = 0; m < 8; m++)
                a2[m] = *(const unsigned long long*)(za + m*40 + 2*kp);
#pragma unroll
            for (int c = 0; c < 4; c++)
                b2[c] = *(const unsigned long long*)(Ws + (tc + 16*c)*WSTR + kb + 2*kp);
#pragma unroll
            for (int m = 0; m < 8; m++)
#pragma unroll
                for (int c = 0; c < 4; c++)
                    asm("fma.rn.f32x2 %0, %1, %2, %0;"
                        : "+l"(acc[m][c]) : "l"(a2[m]), "l"(b2[c]));
        }
        __syncthreads();
    }

#pragma unroll
    for (int m = 0; m < 8; m++) {
        size_t row = row0 + tr*8 + m;
#pragma unroll
        for (int c = 0; c < 4; c++) {
            float lo, hi;
            asm("mov.b64 {%0,%1}, %2;" : "=f"(lo), "=f"(hi) : "l"(acc[m][c]));
            y[row*64 + tc + 16*c] = lo + hi;
        }
    }
}

extern "C" void kernel_launch(void* const* d_in, const int* in_sizes, int n_in,
                              void* d_out, int out_size) {
    const float* x  = (const float*)d_in[0];
    const float* ll = (const float*)d_in[1];
    const float* p  = (const float*)d_in[2];
    const float* q  = (const float*)d_in[3];
    const float* B  = (const float*)d_in[4];
    const float* C  = (const float*)d_in[5];
    const float* D  = (const float*)d_in[6];
    const float* P  = (const float*)d_in[7];
    float* y = (float*)d_out;

    k0_setup<<<1, 256>>>(ll, p, q, B, P);
    knop<<<1, 32>>>();
    knop<<<1, 32>>>();
    kbxs<<<(NBATCH*SEQLEN)/128, 256>>>(x);      // profiled slot (4th)
    k2a<<<NBATCH*NSC/16, 256>>>();
    k2b<<<2, 256>>>();
    k2c<<<NBATCH*NSC, 256>>>();
    dim3 g25(NBATCH*NCH/K25_CHUNKS, LCH/16);
    k25c<<<g25, 256>>>();
    k3_out<<<(NBATCH*SEQLEN)/128, 256>>>(x, C, D, y);
}

// round 12
// speedup vs baseline: 1.0712x; 1.0230x over previous
#include <cuda_runtime.h>
#include <math.h>

#define SD     16
#define IDIM   64
#define ODIM   64
#define NBATCH 32
#define SEQLEN 8192
#define LCH    32
#define NCH    (SEQLEN/LCH)          /* 256 chunks per batch */
#define NSUP   16
#define NSC    (NCH/NSUP)
#define DTVAL  1.0f
#define FULLMASK 0xffffffffu

__device__ __align__(16) float g_Ad[SD*SD];
__device__ __align__(16) float g_Bd[SD*IDIM];
__device__ __align__(16) float g_Apow[LCH*SD*SD];          // A^{j+1}, j=0..31
__device__ __align__(16) float g_ALpow[17*SD*SD];          // (A^32)^j, j=0..16
__device__ __align__(16) float g_H[NBATCH*SEQLEN*SD];
__device__ __align__(16) float g_Pfx[NBATCH*NSC*17*SD];
__device__ __align__(16) float g_Hsup[NBATCH*NSC*SD];

__global__ void knop() {}

// ---------------- K0: discretization + power tables (1 block, 256 thr) ----------------
__global__ void k0_setup(const float* __restrict__ ll, const float* __restrict__ p,
                         const float* __restrict__ q,  const float* __restrict__ B,
                         const float* __restrict__ P) {
    __shared__ float core[SD*SD], tmp[SD*SD], Ac[SD*SD];
    __shared__ float aug[SD][96];
    __shared__ float fvec[SD];
    __shared__ float prow[96];
    int t = threadIdx.x;

    if (t < SD*SD) {
        int i = t >> 4, j = t & 15;
        float v = p[i] * q[j];
        if (i == j) v -= expf(ll[i]);
        core[t] = v;
    }
    __syncthreads();
    if (t < SD*SD) {
        int i = t >> 4, j = t & 15;
        float s = 0.f;
        for (int k = 0; k < SD; k++) s += P[i*SD+k] * core[k*SD+j];
        tmp[t] = s;
    }
    __syncthreads();
    if (t < SD*SD) {
        int i = t >> 4, j = t & 15;
        float s = 0.f;
        for (int k = 0; k < SD; k++) s += tmp[i*SD+k] * P[j*SD+k];
        Ac[t] = s;
    }
    __syncthreads();
    for (int f = t; f < SD*96; f += 256) {
        int r = f / 96, c = f % 96;
        float v;
        if (c < 16)      v = (r == c      ? 1.f : 0.f) - 0.5f*DTVAL*Ac[r*SD+c];
        else if (c < 32) v = (r == (c-16) ? 1.f : 0.f) + 0.5f*DTVAL*Ac[r*SD+(c-16)];
        else             v = DTVAL * B[r*IDIM + (c-32)];
        aug[r][c] = v;
    }
    __syncthreads();
    for (int col = 0; col < SD; col++) {
        if (t < 96) prow[t] = aug[col][t];
        if (t < SD) fvec[t] = aug[t][col];
        __syncthreads();
        float ipv = 1.f / prow[col];
        for (int f = t; f < SD*96; f += 256) {
            int r = f / 96, c = f % 96;
            if (r == col) aug[r][c] = prow[c] * ipv;
            else          aug[r][c] = fmaf(-fvec[r]*ipv, prow[c], aug[r][c]);
        }
        __syncthreads();
    }
    if (t < SD*SD) { int r = t >> 4, c = t & 15; float v = aug[r][16+c]; g_Ad[t] = v; g_Apow[t] = v; }
    for (int f = t; f < SD*IDIM; f += 256) { int r = f / IDIM, c = f % IDIM; g_Bd[f] = aug[r][32+c]; }
    __syncthreads();
    for (int m = 1; m <= LCH/2; m <<= 1) {
        for (int f = t; f < m*256; f += 256) {
            int i = f >> 8, e = f & 255, r = e >> 4, c2 = e & 15;
            const float* L = g_Apow + i*256 + r*16;
            const float* R = g_Apow + (m-1)*256;
            float s = 0.f;
#pragma unroll
            for (int k = 0; k < 16; k++) s = fmaf(L[k], R[k*16 + c2], s);
            g_Apow[(m+i)*256 + e] = s;
        }
        __syncthreads();
    }
    if (t < 256) {
        int r = t >> 4, c = t & 15;
        g_ALpow[t] = (r == c) ? 1.f : 0.f;
        g_ALpow[256 + t] = g_Apow[(LCH-1)*256 + t];
    }
    __syncthreads();
    for (int m = 1; m <= 8; m <<= 1) {
        for (int f = t; f < m*256; f += 256) {
            int i = (f >> 8) + 1, e = f & 255, r = e >> 4, c2 = e & 15;
            const float* L = g_ALpow + i*256 + r*16;
            const float* R = g_ALpow + m*256;
            float s = 0.f;
#pragma unroll
            for (int k = 0; k < 16; k++) s = fmaf(L[k], R[k*16 + c2], s);
            g_ALpow[(m+i)*256 + e] = s;
        }
        __syncthreads();
    }
}

// ---------------- kBxS: u = x @ Bd^T (4x4 f32x2 tile) + in-smem local scan ----------------
#define XSTR 66
#define USTR 20
__global__ void __launch_bounds__(256) kbxs(const float* __restrict__ x) {
    __shared__ __align__(16) float Xs[128*XSTR];   // 33.8 KB, reused as Us
    __shared__ float Bs[16*66];
    __shared__ float As[16*17];
    int tid = threadIdx.x;
    size_t row0 = (size_t)blockIdx.x * 128;

    for (int i = tid; i < SD*IDIM; i += 256) {
        int nn = i >> 6, kk = i & 63;
        Bs[nn*66 + kk] = g_Bd[i];
    }
    if (tid < SD*SD) As[(tid >> 4)*17 + (tid & 15)] = g_Ad[tid];
#pragma unroll
    for (int i = 0; i < 16; i++) {
        int f = tid + 256*i;                  // 4096 float2
        int r = f >> 5, qq = f & 31;
        float2 v = *(const float2*)(x + (row0 + r)*64 + qq*2);
        *(float2*)&Xs[r*XSTR + qq*2] = v;
    }
    __syncthreads();

    // GEMM: threads 0-127, 4 rows x 4 cols (cols tc+4c), f32x2 packed over k
    unsigned long long acc[4][4];
    int tr = tid >> 2, tc = tid & 3;
    if (tid < 128) {
#pragma unroll
        for (int m = 0; m < 4; m++)
#pragma unroll
            for (int c = 0; c < 4; c++) acc[m][c] = 0ull;
        const float* xa = Xs + (tr*4)*XSTR;
#pragma unroll
        for (int kp = 0; kp < 32; kp++) {
            unsigned long long a2[4], b2[4];
#pragma unroll
            for (int m = 0; m < 4; m++)
                a2[m] = *(const unsigned long long*)(xa + m*XSTR + 2*kp);
#pragma unroll
            for (int c = 0; c < 4; c++)
                b2[c] = *(const unsigned long long*)(Bs + (tc + 4*c)*66 + 2*kp);
#pragma unroll
            for (int m = 0; m < 4; m++)
#pragma unroll
                for (int c = 0; c < 4; c++)
                    asm("fma.rn.f32x2 %0, %1, %2, %0;"
                        : "+l"(acc[m][c]) : "l"(a2[m]), "l"(b2[c]));
        }
    }
    __syncthreads();                          // all Xs reads done
    float* Us = Xs;                           // reuse as 128 x USTR
    if (tid < 128) {
#pragma unroll
        for (int m = 0; m < 4; m++)
#pragma unroll
            for (int c = 0; c < 4; c++) {
                float lo, hi;
                asm("mov.b64 {%0,%1}, %2;" : "=f"(lo), "=f"(hi) : "l"(acc[m][c]));
                Us[(tr*4 + m)*USTR + tc + 4*c] = lo + hi;
            }
    }
    __syncthreads();

    // local scan: warps 0-1, half-warp per 32-chunk
    if (tid < 64) {
        int hw = tid >> 4, n = tid & 15;
        float Ar[16];
#pragma unroll
        for (int k = 0; k < 16; k++) Ar[k] = As[n*17 + k];
        float* u = Us + hw*32*USTR + n;
        float h = 0.f;
        float uc = u[0];
#pragma unroll
        for (int i = 0; i < LCH; i++) {
            float un = (i < LCH-1) ? u[(i+1)*USTR] : 0.f;
            float acc0 = uc, acc1 = 0.f, acc2 = 0.f, acc3 = 0.f;
#pragma unroll
            for (int m = 0; m < 16; m += 4) {
                acc0 = fmaf(Ar[m],   __shfl_sync(FULLMASK, h, m,   16), acc0);
                acc1 = fmaf(Ar[m+1], __shfl_sync(FULLMASK, h, m+1, 16), acc1);
                acc2 = fmaf(Ar[m+2], __shfl_sync(FULLMASK, h, m+2, 16), acc2);
                acc3 = fmaf(Ar[m+3], __shfl_sync(FULLMASK, h, m+3, 16), acc3);
            }
            h = (acc0 + acc1) + (acc2 + acc3);
            u[i*USTR] = h;
            uc = un;
        }
    }
    __syncthreads();

#pragma unroll
    for (int i = 0; i < 2; i++) {
        int f = tid + 256*i;
        int r = f >> 2, qq = f & 3;
        float4 v = *(const float4*)&Us[r*USTR + qq*4];
        *(float4*)(g_H + row0*SD + (size_t)f*4) = v;
    }
}

// ---------------- k2a: local prefixes within superchunks (512 half-warps) ----------------
__global__ void __launch_bounds__(256) k2a() {
    int tid = threadIdx.x;
    int g = blockIdx.x * 16 + (tid >> 4);
    int n = tid & 15;
    float Ar[16];
#pragma unroll
    for (int k = 0; k < 16; k++) Ar[k] = g_ALpow[256 + n*16 + k];

    float Pv = 0.f;
#pragma unroll
    for (int j = 0; j < NSUP; j++) {
        g_Pfx[(g*17 + j)*16 + n] = Pv;
        int c = g*NSUP + j;
        float s = g_H[((size_t)c*LCH + (LCH-1))*SD + n];
        float acc0 = s, acc1 = 0.f, acc2 = 0.f, acc3 = 0.f;
#pragma unroll
        for (int m = 0; m < 16; m += 4) {
            acc0 = fmaf(Ar[m],   __shfl_sync(FULLMASK, Pv, m,   16), acc0);
            acc1 = fmaf(Ar[m+1], __shfl_sync(FULLMASK, Pv, m+1, 16), acc1);
            acc2 = fmaf(Ar[m+2], __shfl_sync(FULLMASK, Pv, m+2, 16), acc2);
            acc3 = fmaf(Ar[m+3], __shfl_sync(FULLMASK, Pv, m+3, 16), acc3);
        }
        Pv = (acc0 + acc1) + (acc2 + acc3);
    }
    g_Pfx[(g*17 + 16)*16 + n] = Pv;
}

// ---------------- k2b: scan across superchunks (half-warp per batch) ----------------
__global__ void __launch_bounds__(256) k2b() {
    int tid = threadIdx.x;
    int b = blockIdx.x * 16 + (tid >> 4);
    int n = tid & 15;
    float Ar[16];
#pragma unroll
    for (int k = 0; k < 16; k++) Ar[k] = g_ALpow[16*256 + n*16 + k];

    float H = 0.f;
#pragma unroll
    for (int s = 0; s < NSC; s++) {
        int g = b*NSC + s;
        g_Hsup[g*16 + n] = H;
        float P16 = g_Pfx[(g*17 + 16)*16 + n];
        float acc0 = P16, acc1 = 0.f, acc2 = 0.f, acc3 = 0.f;
#pragma unroll
        for (int m = 0; m < 16; m += 4) {
            acc0 = fmaf(Ar[m],   __shfl_sync(FULLMASK, H, m,   16), acc0);
            acc1 = fmaf(Ar[m+1], __shfl_sync(FULLMASK, H, m+1, 16), acc1);
            acc2 = fmaf(Ar[m+2], __shfl_sync(FULLMASK, H, m+2, 16), acc2);
            acc3 = fmaf(Ar[m+3], __shfl_sync(FULLMASK, H, m+3, 16), acc3);
        }
        H = (acc0 + acc1) + (acc2 + acc3);
    }
}

// ---------------- k25d: hprev reconstruction + h_j += A^{j+1} h_prev ----------------
#define K25_CHUNKS 8
#define PROW 17
__global__ void __launch_bounds__(256) k25d() {
    __shared__ float sA[16*16*PROW];           // A^{1+by*16+jl}
    __shared__ float sAL[8*16*PROW];           // AL^{jbase+jl}
    __shared__ float sHs[16];
    __shared__ float shp[K25_CHUNKS*16];
    int t = threadIdx.x;
    int bx = blockIdx.x, by = blockIdx.y;
    int g = bx >> 1, jbase = (bx & 1) * 8;
    int jloc = t >> 4, n = t & 15;

#pragma unroll
    for (int i = 0; i < 16; i++) {
        int f = t + 256*i;
        int jl = f >> 8, e = f & 255;
        sA[jl*(16*PROW) + (e >> 4)*PROW + (e & 15)] = g_Apow[(by*16 + jl)*256 + e];
    }
#pragma unroll
    for (int i = 0; i < 8; i++) {
        int f = t + 256*i;
        int jl = f >> 8, e = f & 255;
        sAL[jl*(16*PROW) + (e >> 4)*PROW + (e & 15)] = g_ALpow[(jbase + jl)*256 + e];
    }
    if (t < 16) sHs[t] = g_Hsup[g*16 + t];
    if (t < K25_CHUNKS*16) shp[t] = g_Pfx[g*272 + jbase*16 + t];
    __syncthreads();

    if (t < K25_CHUNKS*16) {                   // hprev_c = AL^{jch} Hsup + P_jch
        int ch = t >> 4, nn = t & 15;
        const float* ar = sAL + ch*(16*PROW) + nn*PROW;
        float s = shp[t];
#pragma unroll
        for (int k = 0; k < 16; k++) s = fmaf(ar[k], sHs[k], s);
        shp[t] = s;
    }
    __syncthreads();

    float a[16];
    {
        const float* Ar = sA + jloc*(16*PROW) + n*PROW;
#pragma unroll
        for (int k = 0; k < 16; k++) a[k] = Ar[k];
    }
#pragma unroll
    for (int ch = 0; ch < K25_CHUNKS; ch++) {
        const float* hp = shp + ch*16;
        float s = 0.f;
#pragma unroll
        for (int k = 0; k < 16; k++) s = fmaf(a[k], hp[k], s);
        g_H[(size_t)(bx*K25_CHUNKS + ch)*(LCH*SD) + by*256 + t] += s;
    }
}

// ---------------- K3: Y = [X|H] @ [D|C]^T with packed f32x2 FMA ----------------
#define WSTR 82
__global__ void __launch_bounds__(256, 2) k3_out(const float* __restrict__ x,
                                                 const float* __restrict__ C,
                                                 const float* __restrict__ D,
                                                 float* __restrict__ y) {
    __shared__ __align__(16) float Zs[128*40];
    __shared__ __align__(16) float Ws[64*WSTR];
    int tid = threadIdx.x;
    size_t row0 = (size_t)blockIdx.x * 128;
    int tr = tid >> 4, tc = tid & 15;

#pragma unroll
    for (int i = 0; i < 8; i++) {
        int f = tid + 256*i;
        int o = f >> 5, k0 = (f & 31) << 1;
        float2 v = *(const float2*)(D + o*64 + k0);
        *(float2*)&Ws[o*WSTR + k0] = v;
    }
#pragma unroll
    for (int i = 0; i < 2; i++) {
        int f = tid + 256*i;
        int o = f >> 3, k0 = (f & 7) << 1;
        float2 v = *(const float2*)(C + o*16 + k0);
        *(float2*)&Ws[o*WSTR + 64 + k0] = v;
    }

    unsigned long long acc[8][4];
#pragma unroll
    for (int m = 0; m < 8; m++)
#pragma unroll
        for (int c = 0; c < 4; c++) acc[m][c] = 0ull;

    const float* za = Zs + (tr*8)*40;

#pragma unroll 1
    for (int h = 0; h < 2; h++) {
        if (h == 0) {
#pragma unroll
            for (int i = 0; i < 5; i++) {
                int f = tid + 256*i;
                int r = f / 10, qq = f % 10;
                float4 v = *(const float4*)(x + (row0 + r)*64 + qq*4);
                *(float4*)&Zs[r*40 + qq*4] = v;
            }
        } else {
#pragma unroll
            for (int i = 0; i < 3; i++) {
                int f = tid + 256*i;
                if (f < 768) {
                    int r = f / 6, qq = f % 6;
                    float4 v = *(const float4*)(x + (row0 + r)*64 + 40 + qq*4);
                    *(float4*)&Zs[r*40 + qq*4] = v;
                }
            }
#pragma unroll
            for (int i = 0; i < 2; i++) {
                int f = tid + 256*i;
                int r = f >> 2, qq = f & 3;
                float4 v = *(const float4*)(g_H + (row0 + r)*16 + qq*4);
                *(float4*)&Zs[r*40 + 24 + qq*4] = v;
            }
        }
        __syncthreads();
        int kb = h * 40;
#pragma unroll
        for (int kp = 0; kp < 20; kp++) {
            unsigned long long a2[8], b2[4];
#pragma unroll
            for (int m = 0; m < 8; m++)
                a2[m] = *(const unsigned long long*)(za + m*40 + 2*kp);
#pragma unroll
            for (int c = 0; c < 4; c++)
                b2[c] = *(const unsigned long long*)(Ws + (tc + 16*c)*WSTR + kb + 2*kp);
#pragma unroll
            for (int m = 0; m < 8; m++)
#pragma unroll
                for (int c = 0; c < 4; c++)
                    asm("fma.rn.f32x2 %0, %1, %2, %0;"
                        : "+l"(acc[m][c]) : "l"(a2[m]), "l"(b2[c]));
        }
        __syncthreads();
    }

#pragma unroll
    for (int m = 0; m < 8; m++) {
        size_t row = row0 + tr*8 + m;
#pragma unroll
        for (int c = 0; c < 4; c++) {
            float lo, hi;
            asm("mov.b64 {%0,%1}, %2;" : "=f"(lo), "=f"(hi) : "l"(acc[m][c]));
            y[row*64 + tc + 16*c] = lo + hi;
        }
    }
}

extern "C" void kernel_launch(void* const* d_in, const int* in_sizes, int n_in,
                              void* d_out, int out_size) {
    const float* x  = (const float*)d_in[0];
    const float* ll = (const float*)d_in[1];
    const float* p  = (const float*)d_in[2];
    const float* q  = (const float*)d_in[3];
    const float* B  = (const float*)d_in[4];
    const float* C  = (const float*)d_in[5];
    const float* D  = (const float*)d_in[6];
    const float* P  = (const float*)d_in[7];
    float* y = (float*)d_out;

    k0_setup<<<1, 256>>>(ll, p, q, B, P);
    knop<<<1, 32>>>();
    knop<<<1, 32>>>();
    kbxs<<<(NBATCH*SEQLEN)/128, 256>>>(x);      // profiled slot (4th)
    k2a<<<NBATCH*NSC/16, 256>>>();
    k2b<<<2, 256>>>();
    dim3 g25(NBATCH*NCH/K25_CHUNKS, LCH/16);
    k25d<<<g25, 256>>>();
    k3_out<<<(NBATCH*SEQLEN)/128, 256>>>(x, C, D, y);
}